// round 15
// baseline (speedup 1.0000x reference)
#include <cuda_runtime.h>
#include <math.h>

// ---------------- problem constants ----------------
#define BGRAPHS 128
#define N0      1024
#define EPG     8192                  // max edges per graph
#define EMAX    1048576
#define NT1     (BGRAPHS * N0)        // 131072
#define K1      820
#define NT2     (BGRAPHS * K1)        // 104960
#define K2      656
#define NT3     (BGRAPHS * K2)        // 83968
#define K3      525

#define POOL_SMEM (9 * 4096 + 1024 + 128 + EPG * 2)  // 54400

typedef unsigned short u16;

// ---------------- device scratch ----------------
__device__ float g_A[NT1 * 64];       // conv output h
__device__ float g_xw[NT1 * 64];      // GEMM output, pre-scaled by dis[row]
__device__ float g_disA[NT1], g_disB[NT1];
__device__ float g_sxws[NT1];         // dis[i] * (h[i]·Wp)
__device__ int   g_rpA[NT1], g_rpB[NT1];   // graph-local rowptr
__device__ int   g_cntA[NT1], g_cntB[NT1];
__device__ u16   g_csrA[EMAX], g_csrB[EMAX];  // graph-local src ids
__device__ int   g_meA[BGRAPHS], g_meB[BGRAPHS];
__device__ int   g_perm[NT1];
__device__ float g_gate[NT1];
// rbuf format per graph: [0:64] encoded max bits (unsigned), [64:128] raw sum
__device__ float g_r1[BGRAPHS * 128], g_r2[BGRAPHS * 128], g_r3[BGRAPHS * 128];

// encode float -> order-preserving unsigned (0 is below every real encode)
__device__ __forceinline__ unsigned encf(float x) {
    unsigned b = __float_as_uint(x);
    return b ^ ((b >> 31) ? 0xFFFFFFFFu : 0x80000000u);
}
__device__ __forceinline__ float decf(unsigned u) {
    unsigned b = (u & 0x80000000u) ? (u ^ 0x80000000u) : ~u;
    return __uint_as_float(b);
}

// ---- block-wide exclusive scan, 1024 threads, one element per thread ----
// warpsums[31] holds the grand total afterwards.
__device__ __forceinline__ void block_exscan_1t(int* data, int* warpsums, int t) {
    int orig = data[t];
    int lane = t & 31, wid = t >> 5;
    int v = orig;
#pragma unroll
    for (int off = 1; off < 32; off <<= 1) {
        int u = __shfl_up_sync(0xffffffffu, v, off);
        if (lane >= off) v += u;
    }
    if (lane == 31) warpsums[wid] = v;
    __syncthreads();
    if (t < 32) {
        int w = warpsums[t];
#pragma unroll
        for (int off = 1; off < 32; off <<= 1) {
            int u = __shfl_up_sync(0xffffffffu, w, off);
            if (lane >= off) w += u;
        }
        warpsums[t] = w;  // inclusive warp totals
    }
    __syncthreads();
    int base = (wid > 0) ? warpsums[wid - 1] : 0;
    data[t] = base + v - orig;
    __syncthreads();
}

// ---------------- stage-1 CSR build + readout-accumulator init ----------
__global__ void __launch_bounds__(1024) k_csr0(
    const int* __restrict__ src, const int* __restrict__ dst,
    int* __restrict__ rowptr, int* __restrict__ cnt, float* __restrict__ dis,
    u16* __restrict__ csr, int* __restrict__ me,
    float* __restrict__ r1, float* __restrict__ r2, float* __restrict__ r3) {
    __shared__ int scnt[1024];
    __shared__ int sofs[1024];
    __shared__ int scur[1024];
    __shared__ int warpsums[32];
    int b = blockIdx.x, t = threadIdx.x;
    int ebase = b * EPG, nbase = b * N0;
    // zero readout accumulators (encoded-max 0 is below all reals; sums 0)
    if (t < 128) {
        r1[b * 128 + t] = 0.f;
        r2[b * 128 + t] = 0.f;
        r3[b * 128 + t] = 0.f;
    }
    scnt[t] = 0;
    __syncthreads();
    for (int e = t; e < EPG; e += 1024)
        atomicAdd(&scnt[dst[ebase + e] - nbase], 1);
    __syncthreads();
    sofs[t] = scnt[t];
    __syncthreads();
    block_exscan_1t(sofs, warpsums, t);
    {
        int c = scnt[t];
        int ex = sofs[t];
        rowptr[nbase + t] = ex;           // graph-local
        cnt[nbase + t] = c;
        dis[nbase + t] = rsqrtf((float)c + 1.0f);
        scur[t] = ex;
    }
    if (t == 0) me[b] = EPG;
    __syncthreads();
    for (int e = t; e < EPG; e += 1024) {
        int d = dst[ebase + e] - nbase;
        int p = atomicAdd(&scur[d], 1);
        csr[ebase + p] = (u16)(src[ebase + e] - nbase);
    }
}

// ---------------- GEMM: C[r] = (gather(A)[r] @ W) * scale[r] ----------------
// GATHER variant also folds the previous stage's readout: per-feature max/sum of
// the staged (gathered+gated) As tile, merged into rbuf by atomics.
template <bool GATHER>
__global__ void __launch_bounds__(256) k_gemm64g(
    const float* __restrict__ A, const float* __restrict__ W,
    const float* __restrict__ scale, const int* __restrict__ perm,
    const float* __restrict__ gate, float* __restrict__ C,
    float* __restrict__ rbuf, int kk) {
    __shared__ float As[64][65];
    __shared__ float Ws[64][64];
    int t = threadIdx.x;
    int r0 = blockIdx.x * 64;
    for (int i = t; i < 4096; i += 256) Ws[i >> 6][i & 63] = W[i];
    for (int i = t; i < 1024; i += 256) {
        int r = i >> 4, c4 = i & 15;
        int g = r0 + r;
        float gt = 1.f;
        int row = g;
        if (GATHER) { row = perm[g]; gt = gate[g]; }
        float4 v = ((const float4*)A)[(size_t)row * 16 + c4];
        As[r][c4 * 4 + 0] = v.x * gt;
        As[r][c4 * 4 + 1] = v.y * gt;
        As[r][c4 * 4 + 2] = v.z * gt;
        As[r][c4 * 4 + 3] = v.w * gt;
    }
    __syncthreads();
    int tx = t & 15, ty = t >> 4;
    float acc[4][4] = {};
#pragma unroll 16
    for (int k = 0; k < 64; k++) {
        float4 w = *(const float4*)&Ws[k][tx * 4];
        float a0 = As[ty * 4 + 0][k];
        float a1 = As[ty * 4 + 1][k];
        float a2 = As[ty * 4 + 2][k];
        float a3 = As[ty * 4 + 3][k];
        acc[0][0] += a0 * w.x; acc[0][1] += a0 * w.y; acc[0][2] += a0 * w.z; acc[0][3] += a0 * w.w;
        acc[1][0] += a1 * w.x; acc[1][1] += a1 * w.y; acc[1][2] += a1 * w.z; acc[1][3] += a1 * w.w;
        acc[2][0] += a2 * w.x; acc[2][1] += a2 * w.y; acc[2][2] += a2 * w.z; acc[2][3] += a2 * w.w;
        acc[3][0] += a3 * w.x; acc[3][1] += a3 * w.y; acc[3][2] += a3 * w.z; acc[3][3] += a3 * w.w;
    }
#pragma unroll
    for (int i = 0; i < 4; i++) {
        int r = r0 + ty * 4 + i;
        float s = scale[r];
        *(float4*)&C[(size_t)r * 64 + tx * 4] =
            make_float4(acc[i][0] * s, acc[i][1] * s, acc[i][2] * s, acc[i][3] * s);
    }
    // ---- fused readout of the As tile (previous stage's pooled rows) ----
    if (GATHER && rbuf != nullptr && t < 128) {
        int g0 = r0 / kk;
        int split = (g0 + 1) * kk - r0;
        if (split > 64) split = 64;
        int seg = t >> 6;          // 0: rows [0,split) graph g0; 1: [split,64) g0+1
        int f = t & 63;
        int lo = seg ? split : 0;
        int hi = seg ? 64 : split;
        if (lo < hi) {
            float mx = -3.402823466e+38f, sm = 0.f;
            for (int r = lo; r < hi; r++) {
                float v = As[r][f];
                mx = fmaxf(mx, v);
                sm += v;
            }
            int gb = seg ? g0 + 1 : g0;
            atomicMax((unsigned*)rbuf + gb * 128 + f, encf(mx));
            atomicAdd(rbuf + gb * 128 + 64 + f, sm);
        }
    }
}

// ---------------- fused aggregation: one warp per node, paired edges ----------
// lanes (half, ll): half in {0,1} takes edges half, half+2, ...; ll = feature quad.
// LDG.128 per lane, 2 edges in flight per warp step, no inter-node divergence.
__global__ void k_agg(const float4* __restrict__ xws4, const int* __restrict__ rowptr,
                      const int* __restrict__ cnt, const float* __restrict__ dis,
                      const u16* __restrict__ csr,
                      const float* __restrict__ bvec, const float* __restrict__ Wp,
                      float4* __restrict__ h4, float* __restrict__ sxws,
                      int n, int n_cur) {
    int w = (blockIdx.x * blockDim.x + threadIdx.x) >> 5;
    if (w >= n) return;
    int lane = threadIdx.x & 31;
    int ll = lane & 15;               // feature quad: features 4*ll..4*ll+3
    int half = lane >> 4;             // which edge of each pair
    int g = w / n_cur;                // graph id
    int nbase = g * n_cur;
    const u16* cs = csr + (size_t)g * EPG;
    int start = rowptr[w], dc = cnt[w];
    float4 a0, a1;
    if (half == 0) a0 = xws4[(size_t)w * 16 + ll];  // self message (pre-scaled)
    else a0 = make_float4(0.f, 0.f, 0.f, 0.f);
    a1 = make_float4(0.f, 0.f, 0.f, 0.f);
    for (int base = 0; base < dc; base += 32) {
        int rem = dc - base;
        int s = (lane < rem) ? (int)cs[start + base + lane] : 0;
        int lim = rem < 32 ? rem : 32;
        int je = half;
        for (; je + 6 < lim; je += 8) {
            int s0 = nbase + __shfl_sync(0xffffffffu, s, je);
            int s1 = nbase + __shfl_sync(0xffffffffu, s, je + 2);
            int s2 = nbase + __shfl_sync(0xffffffffu, s, je + 4);
            int s3 = nbase + __shfl_sync(0xffffffffu, s, je + 6);
            float4 v0 = xws4[(size_t)s0 * 16 + ll];
            float4 v1 = xws4[(size_t)s1 * 16 + ll];
            float4 v2 = xws4[(size_t)s2 * 16 + ll];
            float4 v3 = xws4[(size_t)s3 * 16 + ll];
            a0.x += v0.x; a0.y += v0.y; a0.z += v0.z; a0.w += v0.w;
            a1.x += v1.x; a1.y += v1.y; a1.z += v1.z; a1.w += v1.w;
            a0.x += v2.x; a0.y += v2.y; a0.z += v2.z; a0.w += v2.w;
            a1.x += v3.x; a1.y += v3.y; a1.z += v3.z; a1.w += v3.w;
        }
        for (; je < lim; je += 2) {
            int sj = nbase + __shfl_sync(0xffffffffu, s, je);
            float4 v = xws4[(size_t)sj * 16 + ll];
            a0.x += v.x; a0.y += v.y; a0.z += v.z; a0.w += v.w;
        }
    }
    float4 acc;
    acc.x = a0.x + a1.x; acc.y = a0.y + a1.y;
    acc.z = a0.z + a1.z; acc.w = a0.w + a1.w;
    // merge halves (lane ^ 16 holds the other parity's partial)
    acc.x += __shfl_xor_sync(0xffffffffu, acc.x, 16);
    acc.y += __shfl_xor_sync(0xffffffffu, acc.y, 16);
    acc.z += __shfl_xor_sync(0xffffffffu, acc.z, 16);
    acc.w += __shfl_xor_sync(0xffffffffu, acc.w, 16);
    float di = dis[w];
    float4 bb = ((const float4*)bvec)[ll];
    float4 o;
    o.x = fmaxf(acc.x * di + bb.x, 0.f);
    o.y = fmaxf(acc.y * di + bb.y, 0.f);
    o.z = fmaxf(acc.z * di + bb.z, 0.f);
    o.w = fmaxf(acc.w * di + bb.w, 0.f);
    if (half == 0) h4[(size_t)w * 16 + ll] = o;
    float4 wp = ((const float4*)Wp)[ll];
    float p = o.x * wp.x + o.y * wp.y + o.z * wp.z + o.w * wp.w;
#pragma unroll
    for (int off = 8; off > 0; off >>= 1) p += __shfl_xor_sync(0xffffffffu, p, off);
    if (lane == 0) sxws[w] = p * di;
}

// ---------------- all-smem per-graph pool, 1024 threads (no readout) ----------
__global__ void __launch_bounds__(1024) k_pool(
    const float* __restrict__ sxws_g, const float* __restrict__ dis_o,
    const int* __restrict__ rp_o, const int* __restrict__ cnt_o,
    const u16* __restrict__ csr_o, const int* __restrict__ me_o,
    const float* __restrict__ bp, int n_cur, int k, int write_next,
    int* __restrict__ perm_g, float* __restrict__ gate_g,
    int* __restrict__ rp_n, int* __restrict__ cnt_n, float* __restrict__ dis_n,
    u16* __restrict__ csr_n, int* __restrict__ me_n) {
    extern __shared__ char smraw[];
    float* sxw = (float*)smraw;               // 1024
    float* ds = sxw + 1024;                   // 1024
    float* sc = ds + 1024;                    // 1024
    unsigned* su = (unsigned*)(sc + 1024);    // 1024
    int* sflag = (int*)(su + 1024);           // 1024
    int* nidx = sflag + 1024;                 // 1024
    int* oldof = nidx + 1024;                 // 1024
    int* rp = oldof + 1024;                   // 1024
    int* cn = rp + 1024;                      // 1024
    int* hist = cn + 1024;                    // 256
    int* warpsums = hist + 256;               // 32
    u16* cs = (u16*)(warpsums + 32);          // EPG (16B-aligned)
    __shared__ int sh_c, sh_base;
    int b = blockIdx.x, t = threadIdx.x;
    int nbase = b * n_cur;
    int me = me_o[b];
    float bp0 = bp[0];
    // 0. stage graph data into smem (one node per thread; CSR copy vectorized)
    if (t < n_cur) {
        int g = nbase + t;
        rp[t] = rp_o[g];
        cn[t] = cnt_o[g];
        ds[t] = dis_o[g];
        sxw[t] = sxws_g[g];
    }
    {
        const uint4* src4 = (const uint4*)(csr_o + (size_t)b * EPG);
        uint4* dst4 = (uint4*)cs;
        int n8 = (me + 7) >> 3;               // u16 x8 per uint4
        for (int e = t; e < n8; e += 1024) dst4[e] = src4[e];
    }
    __syncthreads();
    // 1. scores (all smem)
    if (t < n_cur) {
        int st = rp[t], dc = cn[t];
        float acc = sxw[t];
        for (int q = 0; q < dc; q++) acc += sxw[cs[st + q]];
        float s = bp0 + ds[t] * acc;
        sc[t] = s;
        su[t] = encf(s);
    }
    __syncthreads();
    // 2. radix select ascending rank R = n_cur - k (the k-th largest key)
    int R = n_cur - k;
    unsigned prefix = 0, maskhi = 0;
#pragma unroll
    for (int pass = 3; pass >= 0; pass--) {
        int shift = pass * 8;
        if (t < 256) hist[t] = 0;
        __syncthreads();
        if (t < n_cur) {
            unsigned u = su[t];
            if ((u & maskhi) == prefix) atomicAdd(&hist[(u >> shift) & 255], 1);
        }
        __syncthreads();
        if (t < 32) {
            int loc[8];
            int s = 0;
#pragma unroll
            for (int j = 0; j < 8; j++) { loc[j] = hist[t * 8 + j]; s += loc[j]; }
            int v = s;
#pragma unroll
            for (int off = 1; off < 32; off <<= 1) {
                int u2 = __shfl_up_sync(0xffffffffu, v, off);
                if ((t & 31) >= off) v += u2;
            }
            int run = v - s;
#pragma unroll
            for (int j = 0; j < 8; j++) {
                if (R >= run && R < run + loc[j]) { sh_c = t * 8 + j; sh_base = run; }
                run += loc[j];
            }
        }
        __syncthreads();
        prefix |= ((unsigned)sh_c) << shift;
        maskhi |= 0xFFu << shift;
        R -= sh_base;
        __syncthreads();
    }
    unsigned thr = prefix;
    // 3. selection flags (gt<<16 | eq), stable compaction by index
    if (t < n_cur) {
        unsigned u = su[t];
        sflag[t] = (((u > thr) ? 1 : 0) << 16) | ((u == thr) ? 1 : 0);
    } else {
        sflag[t] = 0;
    }
    __syncthreads();
    block_exscan_1t(sflag, warpsums, t);
    int tot = warpsums[31];
    int quota = k - (tot >> 16);
    if (t < n_cur) {
        unsigned u = su[t];
        int ex = sflag[t];
        int gtex = ex >> 16, eqex = ex & 0xFFFF;
        int sel = -1;
        if (u > thr) sel = gtex + (eqex < quota ? eqex : quota);
        else if (u == thr && eqex < quota) sel = gtex + eqex;
        nidx[t] = sel;
        if (sel >= 0) oldof[sel] = t;
    } else {
        nidx[t] = -1;
    }
    __syncthreads();
    // 4. gates + perm
    if (t < n_cur) {
        int sel = nidx[t];
        if (sel >= 0) {
            perm_g[b * k + sel] = nbase + t;
            gate_g[b * k + sel] = tanhf(sc[t]);
        }
    }
    if (!write_next) return;
    __syncthreads();
    // 5. surviving-neighbor counts per new node (smem walk)
    if (t < k) {
        int ol = oldof[t];
        int st = rp[ol], dc = cn[ol];
        int c = 0;
        for (int q = 0; q < dc; q++)
            if (nidx[cs[st + q]] >= 0) c++;
        sflag[t] = c;
        cnt_n[b * k + t] = c;
        dis_n[b * k + t] = rsqrtf((float)c + 1.0f);
    } else {
        sflag[t] = 0;
    }
    __syncthreads();
    block_exscan_1t(sflag, warpsums, t);
    if (t == 0) me_n[b] = warpsums[31];
    // 6. write filtered + renamed CSR (u16 local)
    if (t < k) {
        int ex = sflag[t];
        rp_n[b * k + t] = ex;  // graph-local
        int ol = oldof[t];
        int st = rp[ol], dc = cn[ol];
        size_t p = (size_t)b * EPG + ex;
        for (int q = 0; q < dc; q++) {
            int nl = nidx[cs[st + q]];
            if (nl >= 0) csr_n[p++] = (u16)nl;
        }
    }
}

// ---------------- stage-3 readout (full-occupancy, 4 CTAs per graph) ----------
__global__ void __launch_bounds__(256) k_readout(
    const float* __restrict__ A, const int* __restrict__ perm,
    const float* __restrict__ gate, int k, float* __restrict__ rbuf) {
    __shared__ float smax[256], ssum[256];
    int b = blockIdx.x >> 2, q = blockIdx.x & 3;
    int t = threadIdx.x;
    int f = t & 63, rg = t >> 6;
    int per = (k + 3) / 4;
    int lo = q * per, hi = lo + per;
    if (hi > k) hi = k;
    float mx = -3.402823466e+38f, sm = 0.f;
    for (int j = lo + rg; j < hi; j += 4) {
        int idx = b * k + j;
        float v = A[(size_t)perm[idx] * 64 + f] * gate[idx];
        mx = fmaxf(mx, v);
        sm += v;
    }
    smax[t] = mx;
    ssum[t] = sm;
    __syncthreads();
    if (t < 64) {
        float m = fmaxf(fmaxf(smax[t], smax[t + 64]), fmaxf(smax[t + 128], smax[t + 192]));
        float s = ssum[t] + ssum[t + 64] + ssum[t + 128] + ssum[t + 192];
        atomicMax((unsigned*)rbuf + b * 128 + f, encf(m));
        atomicAdd(rbuf + b * 128 + 64 + f, s);
    }
}

// ---------------- final MLP (decodes encoded rbufs) ----------------
__global__ void k_mlp(const float* __restrict__ r1, const float* __restrict__ r2,
                      const float* __restrict__ r3,
                      const float* __restrict__ L1w, const float* __restrict__ L1b,
                      const float* __restrict__ L2w, const float* __restrict__ L2b,
                      const float* __restrict__ L3w, const float* __restrict__ L3b,
                      float* __restrict__ out) {
    __shared__ float zs[128], h1[64], h2[32], os[10];
    __shared__ float lse;
    int b = blockIdx.x, t = threadIdx.x;
    const unsigned* r1u = (const unsigned*)r1;
    const unsigned* r2u = (const unsigned*)r2;
    const unsigned* r3u = (const unsigned*)r3;
    zs[t] = decf(r1u[b * 128 + t]) + decf(r2u[b * 128 + t]) + decf(r3u[b * 128 + t]);
    zs[t + 64] = r1[b * 128 + 64 + t] / (float)K1 +
                 r2[b * 128 + 64 + t] / (float)K2 +
                 r3[b * 128 + 64 + t] / (float)K3;
    __syncthreads();
    {
        float acc = L1b[t];
        for (int j = 0; j < 128; j++) acc += zs[j] * L1w[j * 64 + t];
        h1[t] = fmaxf(acc, 0.f);
    }
    __syncthreads();
    if (t < 32) {
        float a = L2b[t];
        for (int j = 0; j < 64; j++) a += h1[j] * L2w[j * 32 + t];
        h2[t] = fmaxf(a, 0.f);
    }
    __syncthreads();
    if (t < 10) {
        float a = L3b[t];
        for (int j = 0; j < 32; j++) a += h2[j] * L3w[j * 10 + t];
        os[t] = a;
    }
    __syncthreads();
    if (t == 0) {
        float mx = os[0];
        for (int j = 1; j < 10; j++) mx = fmaxf(mx, os[j]);
        float s = 0.f;
        for (int j = 0; j < 10; j++) s += expf(os[j] - mx);
        lse = mx + logf(s);
    }
    __syncthreads();
    if (t < 10) out[b * 10 + t] = os[t] - lse;
}

// ---------------- host orchestration ----------------
extern "C" void kernel_launch(void* const* d_in, const int* in_sizes, int n_in,
                              void* d_out, int out_size) {
    const float* x   = (const float*)d_in[0];
    const int* esrc  = (const int*)d_in[1];
    const int* edst  = (const int*)d_in[2];
    const float* W1  = (const float*)d_in[3];
    const float* b1  = (const float*)d_in[4];
    const float* Wp1 = (const float*)d_in[5];
    const float* bp1 = (const float*)d_in[6];
    const float* W2  = (const float*)d_in[7];
    const float* b2  = (const float*)d_in[8];
    const float* Wp2 = (const float*)d_in[9];
    const float* bp2 = (const float*)d_in[10];
    const float* W3  = (const float*)d_in[11];
    const float* b3  = (const float*)d_in[12];
    const float* Wp3 = (const float*)d_in[13];
    const float* bp3 = (const float*)d_in[14];
    const float* L1w = (const float*)d_in[15];
    const float* L1b = (const float*)d_in[16];
    const float* L2w = (const float*)d_in[17];
    const float* L2b = (const float*)d_in[18];
    const float* L3w = (const float*)d_in[19];
    const float* L3b = (const float*)d_in[20];
    float* out = (float*)d_out;

    cudaFuncSetAttribute(k_pool, cudaFuncAttributeMaxDynamicSharedMemorySize,
                         POOL_SMEM);

    float *pA, *pxw, *pdisA, *pdisB, *psxws, *pgate, *pr1, *pr2, *pr3;
    int *prpA, *prpB, *pcntA, *pcntB, *pmeA, *pmeB, *pperm;
    u16 *pcsrA, *pcsrB;
    cudaGetSymbolAddress((void**)&pA, g_A);
    cudaGetSymbolAddress((void**)&pxw, g_xw);
    cudaGetSymbolAddress((void**)&pdisA, g_disA);
    cudaGetSymbolAddress((void**)&pdisB, g_disB);
    cudaGetSymbolAddress((void**)&psxws, g_sxws);
    cudaGetSymbolAddress((void**)&pgate, g_gate);
    cudaGetSymbolAddress((void**)&pperm, g_perm);
    cudaGetSymbolAddress((void**)&prpA, g_rpA);
    cudaGetSymbolAddress((void**)&prpB, g_rpB);
    cudaGetSymbolAddress((void**)&pcntA, g_cntA);
    cudaGetSymbolAddress((void**)&pcntB, g_cntB);
    cudaGetSymbolAddress((void**)&pcsrA, g_csrA);
    cudaGetSymbolAddress((void**)&pcsrB, g_csrB);
    cudaGetSymbolAddress((void**)&pmeA, g_meA);
    cudaGetSymbolAddress((void**)&pmeB, g_meB);
    cudaGetSymbolAddress((void**)&pr1, g_r1);
    cudaGetSymbolAddress((void**)&pr2, g_r2);
    cudaGetSymbolAddress((void**)&pr3, g_r3);

    // CSR build + readout-accumulator zeroing (no separate memsets)
    k_csr0<<<BGRAPHS, 1024>>>(esrc, edst, prpA, pcntA, pdisA, pcsrA, pmeA,
                              pr1, pr2, pr3);

    // ---- stage 1 ----
    k_gemm64g<false><<<NT1 / 64, 256>>>(x, W1, pdisA, nullptr, nullptr, pxw,
                                        nullptr, 0);
    k_agg<<<NT1 / 8, 256>>>((const float4*)pxw, prpA, pcntA, pdisA, pcsrA,
                            b1, Wp1, (float4*)pA, psxws, NT1, N0);
    k_pool<<<BGRAPHS, 1024, POOL_SMEM>>>(psxws, pdisA, prpA, pcntA, pcsrA,
                                         pmeA, bp1, N0, K1, 1, pperm, pgate,
                                         prpB, pcntB, pdisB, pcsrB, pmeB);

    // ---- stage 2 (gemm computes r1 from its gathered+gated As tiles) ----
    k_gemm64g<true><<<NT2 / 64, 256>>>(pA, W2, pdisB, pperm, pgate, pxw, pr1, K1);
    k_agg<<<NT2 / 8, 256>>>((const float4*)pxw, prpB, pcntB, pdisB, pcsrB,
                            b2, Wp2, (float4*)pA, psxws, NT2, K1);
    k_pool<<<BGRAPHS, 1024, POOL_SMEM>>>(psxws, pdisB, prpB, pcntB, pcsrB,
                                         pmeB, bp2, K1, K2, 1, pperm, pgate,
                                         prpA, pcntA, pdisA, pcsrA, pmeA);

    // ---- stage 3 (gemm computes r2; dedicated kernel computes r3) ----
    k_gemm64g<true><<<NT3 / 64, 256>>>(pA, W3, pdisA, pperm, pgate, pxw, pr2, K2);
    k_agg<<<NT3 / 8, 256>>>((const float4*)pxw, prpA, pcntA, pdisA, pcsrA,
                            b3, Wp3, (float4*)pA, psxws, NT3, K2);
    k_pool<<<BGRAPHS, 1024, POOL_SMEM>>>(psxws, pdisA, prpA, pcntA, pcsrA,
                                         pmeA, bp3, K2, K3, 0, pperm, pgate,
                                         prpB, pcntB, pdisB, pcsrB, pmeB);
    k_readout<<<BGRAPHS * 4, 256>>>(pA, pperm, pgate, K3, pr3);

    k_mlp<<<BGRAPHS, 64>>>(pr1, pr2, pr3, L1w, L1b, L2w, L2b, L3w, L3b, out);
}

// round 16
// speedup vs baseline: 1.4638x; 1.4638x over previous
#include <cuda_runtime.h>
#include <math.h>

// ---------------- problem constants ----------------
#define BGRAPHS 128
#define N0      1024
#define EPG     8192                  // max edges per graph
#define EMAX    1048576
#define NT1     (BGRAPHS * N0)        // 131072
#define K1      820
#define NT2     (BGRAPHS * K1)        // 104960
#define K2      656
#define NT3     (BGRAPHS * K2)        // 83968
#define K3      525

#define POOL_SMEM (9 * 4096 + 1024 + 128 + EPG * 2)  // 54400

typedef unsigned short u16;

// ---------------- device scratch ----------------
__device__ float g_A[NT1 * 64];       // conv output h
__device__ float g_xw[NT1 * 64];      // GEMM output, pre-scaled by dis[row]
__device__ float g_disA[NT1], g_disB[NT1];
__device__ float g_sxws[NT1];         // dis[i] * (h[i]·Wp)
__device__ int   g_rpA[NT1], g_rpB[NT1];   // graph-local rowptr
__device__ int   g_cntA[NT1], g_cntB[NT1];
__device__ u16   g_csrA[EMAX], g_csrB[EMAX];  // graph-local src ids
__device__ int   g_meA[BGRAPHS], g_meB[BGRAPHS];
__device__ int   g_perm[NT1];
__device__ float g_gate[NT1];
// rbuf format per graph: [0:64] encoded max bits (unsigned), [64:128] raw sum
__device__ float g_r1[BGRAPHS * 128], g_r2[BGRAPHS * 128], g_r3[BGRAPHS * 128];

// encode float -> order-preserving unsigned (0 is below every real encode)
__device__ __forceinline__ unsigned encf(float x) {
    unsigned b = __float_as_uint(x);
    return b ^ ((b >> 31) ? 0xFFFFFFFFu : 0x80000000u);
}
__device__ __forceinline__ float decf(unsigned u) {
    unsigned b = (u & 0x80000000u) ? (u ^ 0x80000000u) : ~u;
    return __uint_as_float(b);
}

// ---- block-wide exclusive scan, 1024 threads, one element per thread ----
// warpsums[31] holds the grand total afterwards.
__device__ __forceinline__ void block_exscan_1t(int* data, int* warpsums, int t) {
    int orig = data[t];
    int lane = t & 31, wid = t >> 5;
    int v = orig;
#pragma unroll
    for (int off = 1; off < 32; off <<= 1) {
        int u = __shfl_up_sync(0xffffffffu, v, off);
        if (lane >= off) v += u;
    }
    if (lane == 31) warpsums[wid] = v;
    __syncthreads();
    if (t < 32) {
        int w = warpsums[t];
#pragma unroll
        for (int off = 1; off < 32; off <<= 1) {
            int u = __shfl_up_sync(0xffffffffu, w, off);
            if (lane >= off) w += u;
        }
        warpsums[t] = w;  // inclusive warp totals
    }
    __syncthreads();
    int base = (wid > 0) ? warpsums[wid - 1] : 0;
    data[t] = base + v - orig;
    __syncthreads();
}

// ---------------- stage-1 CSR build + readout-accumulator init ----------
__global__ void __launch_bounds__(1024) k_csr0(
    const int* __restrict__ src, const int* __restrict__ dst,
    int* __restrict__ rowptr, int* __restrict__ cnt, float* __restrict__ dis,
    u16* __restrict__ csr, int* __restrict__ me,
    float* __restrict__ r1, float* __restrict__ r2, float* __restrict__ r3) {
    __shared__ int scnt[1024];
    __shared__ int sofs[1024];
    __shared__ int scur[1024];
    __shared__ int warpsums[32];
    int b = blockIdx.x, t = threadIdx.x;
    int ebase = b * EPG, nbase = b * N0;
    // zero readout accumulators (encoded-max 0 is below all reals; sums 0)
    if (t < 128) {
        r1[b * 128 + t] = 0.f;
        r2[b * 128 + t] = 0.f;
        r3[b * 128 + t] = 0.f;
    }
    scnt[t] = 0;
    __syncthreads();
    for (int e = t; e < EPG; e += 1024)
        atomicAdd(&scnt[dst[ebase + e] - nbase], 1);
    __syncthreads();
    sofs[t] = scnt[t];
    __syncthreads();
    block_exscan_1t(sofs, warpsums, t);
    {
        int c = scnt[t];
        int ex = sofs[t];
        rowptr[nbase + t] = ex;           // graph-local
        cnt[nbase + t] = c;
        dis[nbase + t] = rsqrtf((float)c + 1.0f);
        scur[t] = ex;
    }
    if (t == 0) me[b] = EPG;
    __syncthreads();
    for (int e = t; e < EPG; e += 1024) {
        int d = dst[ebase + e] - nbase;
        int p = atomicAdd(&scur[d], 1);
        csr[ebase + p] = (u16)(src[ebase + e] - nbase);
    }
}

// ---------------- GEMM: C[r] = (gather(A)[r] @ W) * scale[r] ----------------
// GATHER variant also folds the previous stage's readout: per-feature max/sum of
// the staged (gathered+gated) As tile, merged into rbuf by atomics.
template <bool GATHER>
__global__ void __launch_bounds__(256) k_gemm64g(
    const float* __restrict__ A, const float* __restrict__ W,
    const float* __restrict__ scale, const int* __restrict__ perm,
    const float* __restrict__ gate, float* __restrict__ C,
    float* __restrict__ rbuf, int kk) {
    __shared__ float As[64][65];
    __shared__ float Ws[64][64];
    int t = threadIdx.x;
    int r0 = blockIdx.x * 64;
    for (int i = t; i < 4096; i += 256) Ws[i >> 6][i & 63] = W[i];
    for (int i = t; i < 1024; i += 256) {
        int r = i >> 4, c4 = i & 15;
        int g = r0 + r;
        float gt = 1.f;
        int row = g;
        if (GATHER) { row = perm[g]; gt = gate[g]; }
        float4 v = ((const float4*)A)[(size_t)row * 16 + c4];
        As[r][c4 * 4 + 0] = v.x * gt;
        As[r][c4 * 4 + 1] = v.y * gt;
        As[r][c4 * 4 + 2] = v.z * gt;
        As[r][c4 * 4 + 3] = v.w * gt;
    }
    __syncthreads();
    int tx = t & 15, ty = t >> 4;
    float acc[4][4] = {};
#pragma unroll 16
    for (int k = 0; k < 64; k++) {
        float4 w = *(const float4*)&Ws[k][tx * 4];
        float a0 = As[ty * 4 + 0][k];
        float a1 = As[ty * 4 + 1][k];
        float a2 = As[ty * 4 + 2][k];
        float a3 = As[ty * 4 + 3][k];
        acc[0][0] += a0 * w.x; acc[0][1] += a0 * w.y; acc[0][2] += a0 * w.z; acc[0][3] += a0 * w.w;
        acc[1][0] += a1 * w.x; acc[1][1] += a1 * w.y; acc[1][2] += a1 * w.z; acc[1][3] += a1 * w.w;
        acc[2][0] += a2 * w.x; acc[2][1] += a2 * w.y; acc[2][2] += a2 * w.z; acc[2][3] += a2 * w.w;
        acc[3][0] += a3 * w.x; acc[3][1] += a3 * w.y; acc[3][2] += a3 * w.z; acc[3][3] += a3 * w.w;
    }
#pragma unroll
    for (int i = 0; i < 4; i++) {
        int r = r0 + ty * 4 + i;
        float s = scale[r];
        *(float4*)&C[(size_t)r * 64 + tx * 4] =
            make_float4(acc[i][0] * s, acc[i][1] * s, acc[i][2] * s, acc[i][3] * s);
    }
    // ---- fused readout of the As tile (previous stage's pooled rows) ----
    if (GATHER && rbuf != nullptr && t < 128) {
        int g0 = r0 / kk;
        int split = (g0 + 1) * kk - r0;
        if (split > 64) split = 64;
        int seg = t >> 6;          // 0: rows [0,split) graph g0; 1: [split,64) g0+1
        int f = t & 63;
        int lo = seg ? split : 0;
        int hi = seg ? 64 : split;
        if (lo < hi) {
            float mx = -3.402823466e+38f, sm = 0.f;
            for (int r = lo; r < hi; r++) {
                float v = As[r][f];
                mx = fmaxf(mx, v);
                sm += v;
            }
            int gb = seg ? g0 + 1 : g0;
            atomicMax((unsigned*)rbuf + gb * 128 + f, encf(mx));
            atomicAdd(rbuf + gb * 128 + 64 + f, sm);
        }
    }
}

// ---------------- fused aggregation (L2-gather, full occupancy, ILP=4) ------
// one warp per node; lane handles features (2*lane, 2*lane+1)
__global__ void k_agg(const float2* __restrict__ xws2, const int* __restrict__ rowptr,
                      const int* __restrict__ cnt, const float* __restrict__ dis,
                      const u16* __restrict__ csr,
                      const float* __restrict__ b, const float* __restrict__ Wp,
                      float2* __restrict__ h2, float* __restrict__ sxws,
                      int n, int n_cur) {
    int w = (blockIdx.x * blockDim.x + threadIdx.x) >> 5;
    if (w >= n) return;
    int lane = threadIdx.x & 31;
    int g = w / n_cur;                    // graph id
    int nbase = g * n_cur;
    const u16* cs = csr + (size_t)g * EPG;
    int start = rowptr[w], dc = cnt[w];
    float2 acc0 = xws2[(size_t)w * 32 + lane];  // self message (pre-scaled by dis)
    float2 acc1 = make_float2(0.f, 0.f);
    for (int base = 0; base < dc; base += 32) {
        int rem = dc - base;
        int s = (lane < rem) ? (int)cs[start + base + lane] : 0;
        int lim = rem < 32 ? rem : 32;
        int j = 0;
        for (; j + 4 <= lim; j += 4) {
            int s0 = nbase + __shfl_sync(0xffffffffu, s, j);
            int s1 = nbase + __shfl_sync(0xffffffffu, s, j + 1);
            int s2 = nbase + __shfl_sync(0xffffffffu, s, j + 2);
            int s3 = nbase + __shfl_sync(0xffffffffu, s, j + 3);
            float2 v0 = xws2[(size_t)s0 * 32 + lane];
            float2 v1 = xws2[(size_t)s1 * 32 + lane];
            float2 v2 = xws2[(size_t)s2 * 32 + lane];
            float2 v3 = xws2[(size_t)s3 * 32 + lane];
            acc0.x += v0.x; acc0.y += v0.y;
            acc1.x += v1.x; acc1.y += v1.y;
            acc0.x += v2.x; acc0.y += v2.y;
            acc1.x += v3.x; acc1.y += v3.y;
        }
        for (; j < lim; j++) {
            int sj = nbase + __shfl_sync(0xffffffffu, s, j);
            float2 v = xws2[(size_t)sj * 32 + lane];
            acc0.x += v.x; acc0.y += v.y;
        }
    }
    float di = dis[w];
    float2 o;
    o.x = fmaxf((acc0.x + acc1.x) * di + b[2 * lane], 0.f);
    o.y = fmaxf((acc0.y + acc1.y) * di + b[2 * lane + 1], 0.f);
    h2[(size_t)w * 32 + lane] = o;
    float sa = o.x * Wp[2 * lane] + o.y * Wp[2 * lane + 1];
#pragma unroll
    for (int off = 16; off > 0; off >>= 1) sa += __shfl_xor_sync(0xffffffffu, sa, off);
    if (lane == 0) sxws[w] = sa * di;
}

// ---------------- all-smem per-graph pool, 1024 threads (no readout) ----------
__global__ void __launch_bounds__(1024) k_pool(
    const float* __restrict__ sxws_g, const float* __restrict__ dis_o,
    const int* __restrict__ rp_o, const int* __restrict__ cnt_o,
    const u16* __restrict__ csr_o, const int* __restrict__ me_o,
    const float* __restrict__ bp, int n_cur, int k, int write_next,
    int* __restrict__ perm_g, float* __restrict__ gate_g,
    int* __restrict__ rp_n, int* __restrict__ cnt_n, float* __restrict__ dis_n,
    u16* __restrict__ csr_n, int* __restrict__ me_n) {
    extern __shared__ char smraw[];
    float* sxw = (float*)smraw;               // 1024
    float* ds = sxw + 1024;                   // 1024
    float* sc = ds + 1024;                    // 1024
    unsigned* su = (unsigned*)(sc + 1024);    // 1024
    int* sflag = (int*)(su + 1024);           // 1024
    int* nidx = sflag + 1024;                 // 1024
    int* oldof = nidx + 1024;                 // 1024
    int* rp = oldof + 1024;                   // 1024
    int* cn = rp + 1024;                      // 1024
    int* hist = cn + 1024;                    // 256
    int* warpsums = hist + 256;               // 32
    u16* cs = (u16*)(warpsums + 32);          // EPG (16B-aligned)
    __shared__ int sh_c, sh_base;
    int b = blockIdx.x, t = threadIdx.x;
    int nbase = b * n_cur;
    int me = me_o[b];
    float bp0 = bp[0];
    // 0. stage graph data into smem (one node per thread; CSR copy vectorized)
    if (t < n_cur) {
        int g = nbase + t;
        rp[t] = rp_o[g];
        cn[t] = cnt_o[g];
        ds[t] = dis_o[g];
        sxw[t] = sxws_g[g];
    }
    {
        const uint4* src4 = (const uint4*)(csr_o + (size_t)b * EPG);
        uint4* dst4 = (uint4*)cs;
        int n8 = (me + 7) >> 3;               // u16 x8 per uint4
        for (int e = t; e < n8; e += 1024) dst4[e] = src4[e];
    }
    __syncthreads();
    // 1. scores (all smem)
    if (t < n_cur) {
        int st = rp[t], dc = cn[t];
        float acc = sxw[t];
        for (int q = 0; q < dc; q++) acc += sxw[cs[st + q]];
        float s = bp0 + ds[t] * acc;
        sc[t] = s;
        su[t] = encf(s);
    }
    __syncthreads();
    // 2. radix select ascending rank R = n_cur - k (the k-th largest key)
    int R = n_cur - k;
    unsigned prefix = 0, maskhi = 0;
#pragma unroll
    for (int pass = 3; pass >= 0; pass--) {
        int shift = pass * 8;
        if (t < 256) hist[t] = 0;
        __syncthreads();
        if (t < n_cur) {
            unsigned u = su[t];
            if ((u & maskhi) == prefix) atomicAdd(&hist[(u >> shift) & 255], 1);
        }
        __syncthreads();
        if (t < 32) {
            int loc[8];
            int s = 0;
#pragma unroll
            for (int j = 0; j < 8; j++) { loc[j] = hist[t * 8 + j]; s += loc[j]; }
            int v = s;
#pragma unroll
            for (int off = 1; off < 32; off <<= 1) {
                int u2 = __shfl_up_sync(0xffffffffu, v, off);
                if ((t & 31) >= off) v += u2;
            }
            int run = v - s;
#pragma unroll
            for (int j = 0; j < 8; j++) {
                if (R >= run && R < run + loc[j]) { sh_c = t * 8 + j; sh_base = run; }
                run += loc[j];
            }
        }
        __syncthreads();
        prefix |= ((unsigned)sh_c) << shift;
        maskhi |= 0xFFu << shift;
        R -= sh_base;
        __syncthreads();
    }
    unsigned thr = prefix;
    // 3. selection flags (gt<<16 | eq), stable compaction by index
    if (t < n_cur) {
        unsigned u = su[t];
        sflag[t] = (((u > thr) ? 1 : 0) << 16) | ((u == thr) ? 1 : 0);
    } else {
        sflag[t] = 0;
    }
    __syncthreads();
    block_exscan_1t(sflag, warpsums, t);
    int tot = warpsums[31];
    int quota = k - (tot >> 16);
    if (t < n_cur) {
        unsigned u = su[t];
        int ex = sflag[t];
        int gtex = ex >> 16, eqex = ex & 0xFFFF;
        int sel = -1;
        if (u > thr) sel = gtex + (eqex < quota ? eqex : quota);
        else if (u == thr && eqex < quota) sel = gtex + eqex;
        nidx[t] = sel;
        if (sel >= 0) oldof[sel] = t;
    } else {
        nidx[t] = -1;
    }
    __syncthreads();
    // 4. gates + perm
    if (t < n_cur) {
        int sel = nidx[t];
        if (sel >= 0) {
            perm_g[b * k + sel] = nbase + t;
            gate_g[b * k + sel] = tanhf(sc[t]);
        }
    }
    if (!write_next) return;
    __syncthreads();
    // 5. surviving-neighbor counts per new node (smem walk)
    if (t < k) {
        int ol = oldof[t];
        int st = rp[ol], dc = cn[ol];
        int c = 0;
        for (int q = 0; q < dc; q++)
            if (nidx[cs[st + q]] >= 0) c++;
        sflag[t] = c;
        cnt_n[b * k + t] = c;
        dis_n[b * k + t] = rsqrtf((float)c + 1.0f);
    } else {
        sflag[t] = 0;
    }
    __syncthreads();
    block_exscan_1t(sflag, warpsums, t);
    if (t == 0) me_n[b] = warpsums[31];
    // 6. write filtered + renamed CSR (u16 local)
    if (t < k) {
        int ex = sflag[t];
        rp_n[b * k + t] = ex;  // graph-local
        int ol = oldof[t];
        int st = rp[ol], dc = cn[ol];
        size_t p = (size_t)b * EPG + ex;
        for (int q = 0; q < dc; q++) {
            int nl = nidx[cs[st + q]];
            if (nl >= 0) csr_n[p++] = (u16)nl;
        }
    }
}

// ---------------- stage-3 readout (full-occupancy, 4 CTAs per graph) ----------
__global__ void __launch_bounds__(256) k_readout(
    const float* __restrict__ A, const int* __restrict__ perm,
    const float* __restrict__ gate, int k, float* __restrict__ rbuf) {
    __shared__ float smax[256], ssum[256];
    int b = blockIdx.x >> 2, q = blockIdx.x & 3;
    int t = threadIdx.x;
    int f = t & 63, rg = t >> 6;
    int per = (k + 3) / 4;
    int lo = q * per, hi = lo + per;
    if (hi > k) hi = k;
    float mx = -3.402823466e+38f, sm = 0.f;
    for (int j = lo + rg; j < hi; j += 4) {
        int idx = b * k + j;
        float v = A[(size_t)perm[idx] * 64 + f] * gate[idx];
        mx = fmaxf(mx, v);
        sm += v;
    }
    smax[t] = mx;
    ssum[t] = sm;
    __syncthreads();
    if (t < 64) {
        float m = fmaxf(fmaxf(smax[t], smax[t + 64]), fmaxf(smax[t + 128], smax[t + 192]));
        float s = ssum[t] + ssum[t + 64] + ssum[t + 128] + ssum[t + 192];
        atomicMax((unsigned*)rbuf + b * 128 + f, encf(m));
        atomicAdd(rbuf + b * 128 + 64 + f, s);
    }
}

// ---------------- final MLP (decodes encoded rbufs) ----------------
__global__ void k_mlp(const float* __restrict__ r1, const float* __restrict__ r2,
                      const float* __restrict__ r3,
                      const float* __restrict__ L1w, const float* __restrict__ L1b,
                      const float* __restrict__ L2w, const float* __restrict__ L2b,
                      const float* __restrict__ L3w, const float* __restrict__ L3b,
                      float* __restrict__ out) {
    __shared__ float zs[128], h1[64], h2[32], os[10];
    __shared__ float lse;
    int b = blockIdx.x, t = threadIdx.x;
    const unsigned* r1u = (const unsigned*)r1;
    const unsigned* r2u = (const unsigned*)r2;
    const unsigned* r3u = (const unsigned*)r3;
    zs[t] = decf(r1u[b * 128 + t]) + decf(r2u[b * 128 + t]) + decf(r3u[b * 128 + t]);
    zs[t + 64] = r1[b * 128 + 64 + t] / (float)K1 +
                 r2[b * 128 + 64 + t] / (float)K2 +
                 r3[b * 128 + 64 + t] / (float)K3;
    __syncthreads();
    {
        float acc = L1b[t];
        for (int j = 0; j < 128; j++) acc += zs[j] * L1w[j * 64 + t];
        h1[t] = fmaxf(acc, 0.f);
    }
    __syncthreads();
    if (t < 32) {
        float a = L2b[t];
        for (int j = 0; j < 64; j++) a += h1[j] * L2w[j * 32 + t];
        h2[t] = fmaxf(a, 0.f);
    }
    __syncthreads();
    if (t < 10) {
        float a = L3b[t];
        for (int j = 0; j < 32; j++) a += h2[j] * L3w[j * 10 + t];
        os[t] = a;
    }
    __syncthreads();
    if (t == 0) {
        float mx = os[0];
        for (int j = 1; j < 10; j++) mx = fmaxf(mx, os[j]);
        float s = 0.f;
        for (int j = 0; j < 10; j++) s += expf(os[j] - mx);
        lse = mx + logf(s);
    }
    __syncthreads();
    if (t < 10) out[b * 10 + t] = os[t] - lse;
}

// ---------------- host orchestration ----------------
extern "C" void kernel_launch(void* const* d_in, const int* in_sizes, int n_in,
                              void* d_out, int out_size) {
    const float* x   = (const float*)d_in[0];
    const int* esrc  = (const int*)d_in[1];
    const int* edst  = (const int*)d_in[2];
    const float* W1  = (const float*)d_in[3];
    const float* b1  = (const float*)d_in[4];
    const float* Wp1 = (const float*)d_in[5];
    const float* bp1 = (const float*)d_in[6];
    const float* W2  = (const float*)d_in[7];
    const float* b2  = (const float*)d_in[8];
    const float* Wp2 = (const float*)d_in[9];
    const float* bp2 = (const float*)d_in[10];
    const float* W3  = (const float*)d_in[11];
    const float* b3  = (const float*)d_in[12];
    const float* Wp3 = (const float*)d_in[13];
    const float* bp3 = (const float*)d_in[14];
    const float* L1w = (const float*)d_in[15];
    const float* L1b = (const float*)d_in[16];
    const float* L2w = (const float*)d_in[17];
    const float* L2b = (const float*)d_in[18];
    const float* L3w = (const float*)d_in[19];
    const float* L3b = (const float*)d_in[20];
    float* out = (float*)d_out;

    cudaFuncSetAttribute(k_pool, cudaFuncAttributeMaxDynamicSharedMemorySize,
                         POOL_SMEM);

    float *pA, *pxw, *pdisA, *pdisB, *psxws, *pgate, *pr1, *pr2, *pr3;
    int *prpA, *prpB, *pcntA, *pcntB, *pmeA, *pmeB, *pperm;
    u16 *pcsrA, *pcsrB;
    cudaGetSymbolAddress((void**)&pA, g_A);
    cudaGetSymbolAddress((void**)&pxw, g_xw);
    cudaGetSymbolAddress((void**)&pdisA, g_disA);
    cudaGetSymbolAddress((void**)&pdisB, g_disB);
    cudaGetSymbolAddress((void**)&psxws, g_sxws);
    cudaGetSymbolAddress((void**)&pgate, g_gate);
    cudaGetSymbolAddress((void**)&pperm, g_perm);
    cudaGetSymbolAddress((void**)&prpA, g_rpA);
    cudaGetSymbolAddress((void**)&prpB, g_rpB);
    cudaGetSymbolAddress((void**)&pcntA, g_cntA);
    cudaGetSymbolAddress((void**)&pcntB, g_cntB);
    cudaGetSymbolAddress((void**)&pcsrA, g_csrA);
    cudaGetSymbolAddress((void**)&pcsrB, g_csrB);
    cudaGetSymbolAddress((void**)&pmeA, g_meA);
    cudaGetSymbolAddress((void**)&pmeB, g_meB);
    cudaGetSymbolAddress((void**)&pr1, g_r1);
    cudaGetSymbolAddress((void**)&pr2, g_r2);
    cudaGetSymbolAddress((void**)&pr3, g_r3);

    // CSR build + readout-accumulator zeroing (no separate memsets)
    k_csr0<<<BGRAPHS, 1024>>>(esrc, edst, prpA, pcntA, pdisA, pcsrA, pmeA,
                              pr1, pr2, pr3);

    // ---- stage 1 ----
    k_gemm64g<false><<<NT1 / 64, 256>>>(x, W1, pdisA, nullptr, nullptr, pxw,
                                        nullptr, 0);
    k_agg<<<NT1 / 8, 256>>>((const float2*)pxw, prpA, pcntA, pdisA, pcsrA,
                            b1, Wp1, (float2*)pA, psxws, NT1, N0);
    k_pool<<<BGRAPHS, 1024, POOL_SMEM>>>(psxws, pdisA, prpA, pcntA, pcsrA,
                                         pmeA, bp1, N0, K1, 1, pperm, pgate,
                                         prpB, pcntB, pdisB, pcsrB, pmeB);

    // ---- stage 2 (gemm computes r1 from its gathered+gated As tiles) ----
    k_gemm64g<true><<<NT2 / 64, 256>>>(pA, W2, pdisB, pperm, pgate, pxw, pr1, K1);
    k_agg<<<NT2 / 8, 256>>>((const float2*)pxw, prpB, pcntB, pdisB, pcsrB,
                            b2, Wp2, (float2*)pA, psxws, NT2, K1);
    k_pool<<<BGRAPHS, 1024, POOL_SMEM>>>(psxws, pdisB, prpB, pcntB, pcsrB,
                                         pmeB, bp2, K1, K2, 1, pperm, pgate,
                                         prpA, pcntA, pdisA, pcsrA, pmeA);

    // ---- stage 3 (gemm computes r2; dedicated kernel computes r3) ----
    k_gemm64g<true><<<NT3 / 64, 256>>>(pA, W3, pdisA, pperm, pgate, pxw, pr2, K2);
    k_agg<<<NT3 / 8, 256>>>((const float2*)pxw, prpA, pcntA, pdisA, pcsrA,
                            b3, Wp3, (float2*)pA, psxws, NT3, K2);
    k_pool<<<BGRAPHS, 1024, POOL_SMEM>>>(psxws, pdisA, prpA, pcntA, pcsrA,
                                         pmeA, bp3, K2, K3, 0, pperm, pgate,
                                         prpB, pcntB, pdisB, pcsrB, pmeB);
    k_readout<<<BGRAPHS * 4, 256>>>(pA, pperm, pgate, K3, pr3);

    k_mlp<<<BGRAPHS, 64>>>(pr1, pr2, pr3, L1w, L1b, L2w, L2b, L3w, L3b, out);
}

// round 17
// speedup vs baseline: 1.4850x; 1.0145x over previous
#include <cuda_runtime.h>
#include <math.h>

// ---------------- problem constants ----------------
#define BGRAPHS 128
#define N0      1024
#define EPG     8192                  // max edges per graph
#define EMAX    1048576
#define NT1     (BGRAPHS * N0)        // 131072
#define K1      820
#define NT2     (BGRAPHS * K1)        // 104960
#define K2      656
#define NT3     (BGRAPHS * K2)        // 83968
#define K3      525

#define POOL_SMEM (9 * 4096 + 1024 + 128 + EPG * 2)  // 54400

typedef unsigned short u16;

// ---------------- device scratch ----------------
__device__ float g_A[NT1 * 64];       // conv output h
__device__ float g_xw[NT1 * 64];      // GEMM output, pre-scaled by dis[row]
__device__ float g_disA[NT1], g_disB[NT1];
__device__ float g_sxws[NT1];         // dis[i] * (h[i]·Wp)
__device__ int   g_rpA[NT1], g_rpB[NT1];   // graph-local rowptr
__device__ int   g_cntA[NT1], g_cntB[NT1];
__device__ u16   g_csrA[EMAX], g_csrB[EMAX];  // graph-local src ids
__device__ int   g_meA[BGRAPHS], g_meB[BGRAPHS];
__device__ int   g_perm[NT1];
__device__ float g_gate[NT1];
// rbuf format per graph: [0:64] encoded max bits (unsigned), [64:128] raw sum
__device__ float g_r1[BGRAPHS * 128], g_r2[BGRAPHS * 128], g_r3[BGRAPHS * 128];

// encode float -> order-preserving unsigned (0 is below every real encode)
__device__ __forceinline__ unsigned encf(float x) {
    unsigned b = __float_as_uint(x);
    return b ^ ((b >> 31) ? 0xFFFFFFFFu : 0x80000000u);
}
__device__ __forceinline__ float decf(unsigned u) {
    unsigned b = (u & 0x80000000u) ? (u ^ 0x80000000u) : ~u;
    return __uint_as_float(b);
}

// ---- block-wide exclusive scan, 1024 threads, one element per thread ----
// warpsums[31] holds the grand total afterwards.
__device__ __forceinline__ void block_exscan_1t(int* data, int* warpsums, int t) {
    int orig = data[t];
    int lane = t & 31, wid = t >> 5;
    int v = orig;
#pragma unroll
    for (int off = 1; off < 32; off <<= 1) {
        int u = __shfl_up_sync(0xffffffffu, v, off);
        if (lane >= off) v += u;
    }
    if (lane == 31) warpsums[wid] = v;
    __syncthreads();
    if (t < 32) {
        int w = warpsums[t];
#pragma unroll
        for (int off = 1; off < 32; off <<= 1) {
            int u = __shfl_up_sync(0xffffffffu, w, off);
            if (lane >= off) w += u;
        }
        warpsums[t] = w;  // inclusive warp totals
    }
    __syncthreads();
    int base = (wid > 0) ? warpsums[wid - 1] : 0;
    data[t] = base + v - orig;
    __syncthreads();
}

// ---------------- stage-1 CSR build + readout-accumulator init ----------
__global__ void __launch_bounds__(1024) k_csr0(
    const int* __restrict__ src, const int* __restrict__ dst,
    int* __restrict__ rowptr, int* __restrict__ cnt, float* __restrict__ dis,
    u16* __restrict__ csr, int* __restrict__ me,
    float* __restrict__ r1, float* __restrict__ r2, float* __restrict__ r3) {
    __shared__ int scnt[1024];
    __shared__ int sofs[1024];
    __shared__ int scur[1024];
    __shared__ int warpsums[32];
    int b = blockIdx.x, t = threadIdx.x;
    int ebase = b * EPG, nbase = b * N0;
    // zero readout accumulators (encoded-max 0 is below all reals; sums 0)
    if (t < 128) {
        r1[b * 128 + t] = 0.f;
        r2[b * 128 + t] = 0.f;
        r3[b * 128 + t] = 0.f;
    }
    scnt[t] = 0;
    __syncthreads();
    for (int e = t; e < EPG; e += 1024)
        atomicAdd(&scnt[dst[ebase + e] - nbase], 1);
    __syncthreads();
    sofs[t] = scnt[t];
    __syncthreads();
    block_exscan_1t(sofs, warpsums, t);
    {
        int c = scnt[t];
        int ex = sofs[t];
        rowptr[nbase + t] = ex;           // graph-local
        cnt[nbase + t] = c;
        dis[nbase + t] = rsqrtf((float)c + 1.0f);
        scur[t] = ex;
    }
    if (t == 0) me[b] = EPG;
    __syncthreads();
    for (int e = t; e < EPG; e += 1024) {
        int d = dst[ebase + e] - nbase;
        int p = atomicAdd(&scur[d], 1);
        csr[ebase + p] = (u16)(src[ebase + e] - nbase);
    }
}

// ---------------- GEMM: C[r] = (gather(A)[r] @ W) * scale[r] ----------------
// GATHER variant also folds the previous stage's readout: per-feature max/sum of
// the staged (gathered+gated) As tile, merged into rbuf by atomics.
template <bool GATHER>
__global__ void __launch_bounds__(256) k_gemm64g(
    const float* __restrict__ A, const float* __restrict__ W,
    const float* __restrict__ scale, const int* __restrict__ perm,
    const float* __restrict__ gate, float* __restrict__ C,
    float* __restrict__ rbuf, int kk) {
    __shared__ float As[64][65];
    __shared__ float Ws[64][64];
    int t = threadIdx.x;
    int r0 = blockIdx.x * 64;
    for (int i = t; i < 4096; i += 256) Ws[i >> 6][i & 63] = W[i];
    for (int i = t; i < 1024; i += 256) {
        int r = i >> 4, c4 = i & 15;
        int g = r0 + r;
        float gt = 1.f;
        int row = g;
        if (GATHER) { row = perm[g]; gt = gate[g]; }
        float4 v = ((const float4*)A)[(size_t)row * 16 + c4];
        As[r][c4 * 4 + 0] = v.x * gt;
        As[r][c4 * 4 + 1] = v.y * gt;
        As[r][c4 * 4 + 2] = v.z * gt;
        As[r][c4 * 4 + 3] = v.w * gt;
    }
    __syncthreads();
    int tx = t & 15, ty = t >> 4;
    float acc[4][4] = {};
#pragma unroll 16
    for (int k = 0; k < 64; k++) {
        float4 w = *(const float4*)&Ws[k][tx * 4];
        float a0 = As[ty * 4 + 0][k];
        float a1 = As[ty * 4 + 1][k];
        float a2 = As[ty * 4 + 2][k];
        float a3 = As[ty * 4 + 3][k];
        acc[0][0] += a0 * w.x; acc[0][1] += a0 * w.y; acc[0][2] += a0 * w.z; acc[0][3] += a0 * w.w;
        acc[1][0] += a1 * w.x; acc[1][1] += a1 * w.y; acc[1][2] += a1 * w.z; acc[1][3] += a1 * w.w;
        acc[2][0] += a2 * w.x; acc[2][1] += a2 * w.y; acc[2][2] += a2 * w.z; acc[2][3] += a2 * w.w;
        acc[3][0] += a3 * w.x; acc[3][1] += a3 * w.y; acc[3][2] += a3 * w.z; acc[3][3] += a3 * w.w;
    }
#pragma unroll
    for (int i = 0; i < 4; i++) {
        int r = r0 + ty * 4 + i;
        float s = scale[r];
        *(float4*)&C[(size_t)r * 64 + tx * 4] =
            make_float4(acc[i][0] * s, acc[i][1] * s, acc[i][2] * s, acc[i][3] * s);
    }
    // ---- fused readout of the As tile (previous stage's pooled rows) ----
    if (GATHER && rbuf != nullptr && t < 128) {
        int g0 = r0 / kk;
        int split = (g0 + 1) * kk - r0;
        if (split > 64) split = 64;
        int seg = t >> 6;          // 0: rows [0,split) graph g0; 1: [split,64) g0+1
        int f = t & 63;
        int lo = seg ? split : 0;
        int hi = seg ? 64 : split;
        if (lo < hi) {
            float mx = -3.402823466e+38f, sm = 0.f;
            for (int r = lo; r < hi; r++) {
                float v = As[r][f];
                mx = fmaxf(mx, v);
                sm += v;
            }
            int gb = seg ? g0 + 1 : g0;
            atomicMax((unsigned*)rbuf + gb * 128 + f, encf(mx));
            atomicAdd(rbuf + gb * 128 + 64 + f, sm);
        }
    }
}

// ---------------- fused aggregation (L2-gather, full occupancy, ILP=4) ------
// one warp per node; lane handles features (2*lane, 2*lane+1)
__global__ void k_agg(const float2* __restrict__ xws2, const int* __restrict__ rowptr,
                      const int* __restrict__ cnt, const float* __restrict__ dis,
                      const u16* __restrict__ csr,
                      const float* __restrict__ b, const float* __restrict__ Wp,
                      float2* __restrict__ h2, float* __restrict__ sxws,
                      int n, int n_cur) {
    int w = (blockIdx.x * blockDim.x + threadIdx.x) >> 5;
    if (w >= n) return;
    int lane = threadIdx.x & 31;
    int g = w / n_cur;                    // graph id
    int nbase = g * n_cur;
    const u16* cs = csr + (size_t)g * EPG;
    int start = rowptr[w], dc = cnt[w];
    float2 acc0 = xws2[(size_t)w * 32 + lane];  // self message (pre-scaled by dis)
    float2 acc1 = make_float2(0.f, 0.f);
    for (int base = 0; base < dc; base += 32) {
        int rem = dc - base;
        int s = (lane < rem) ? (int)cs[start + base + lane] : 0;
        int lim = rem < 32 ? rem : 32;
        int j = 0;
        for (; j + 4 <= lim; j += 4) {
            int s0 = nbase + __shfl_sync(0xffffffffu, s, j);
            int s1 = nbase + __shfl_sync(0xffffffffu, s, j + 1);
            int s2 = nbase + __shfl_sync(0xffffffffu, s, j + 2);
            int s3 = nbase + __shfl_sync(0xffffffffu, s, j + 3);
            float2 v0 = xws2[(size_t)s0 * 32 + lane];
            float2 v1 = xws2[(size_t)s1 * 32 + lane];
            float2 v2 = xws2[(size_t)s2 * 32 + lane];
            float2 v3 = xws2[(size_t)s3 * 32 + lane];
            acc0.x += v0.x; acc0.y += v0.y;
            acc1.x += v1.x; acc1.y += v1.y;
            acc0.x += v2.x; acc0.y += v2.y;
            acc1.x += v3.x; acc1.y += v3.y;
        }
        for (; j < lim; j++) {
            int sj = nbase + __shfl_sync(0xffffffffu, s, j);
            float2 v = xws2[(size_t)sj * 32 + lane];
            acc0.x += v.x; acc0.y += v.y;
        }
    }
    float di = dis[w];
    float2 o;
    o.x = fmaxf((acc0.x + acc1.x) * di + b[2 * lane], 0.f);
    o.y = fmaxf((acc0.y + acc1.y) * di + b[2 * lane + 1], 0.f);
    h2[(size_t)w * 32 + lane] = o;
    float sa = o.x * Wp[2 * lane] + o.y * Wp[2 * lane + 1];
#pragma unroll
    for (int off = 16; off > 0; off >>= 1) sa += __shfl_xor_sync(0xffffffffu, sa, off);
    if (lane == 0) sxws[w] = sa * di;
}

// ---------------- all-smem per-graph pool, 1024 threads ----------------
// write_next=1: emit filtered CSR + perm/gate for the next stage's GEMM.
// write_next=0: final stage — fused readout (max/mean of gated h) into rbuf.
__global__ void __launch_bounds__(1024) k_pool(
    const float* __restrict__ A, const float* __restrict__ sxws_g,
    const float* __restrict__ dis_o,
    const int* __restrict__ rp_o, const int* __restrict__ cnt_o,
    const u16* __restrict__ csr_o, const int* __restrict__ me_o,
    const float* __restrict__ bp, int n_cur, int k, int write_next,
    int* __restrict__ perm_g, float* __restrict__ gate_g,
    float* __restrict__ rbuf,
    int* __restrict__ rp_n, int* __restrict__ cnt_n, float* __restrict__ dis_n,
    u16* __restrict__ csr_n, int* __restrict__ me_n) {
    extern __shared__ char smraw[];
    float* sxw = (float*)smraw;               // 1024
    float* ds = sxw + 1024;                   // 1024
    float* sc = ds + 1024;                    // 1024
    unsigned* su = (unsigned*)(sc + 1024);    // 1024
    int* sflag = (int*)(su + 1024);           // 1024 (reused as rred in readout)
    int* nidx = sflag + 1024;                 // 1024
    int* oldof = nidx + 1024;                 // 1024
    int* rp = oldof + 1024;                   // 1024
    int* cn = rp + 1024;                      // 1024
    int* hist = cn + 1024;                    // 256
    int* warpsums = hist + 256;               // 32
    u16* cs = (u16*)(warpsums + 32);          // EPG (16B-aligned)
    __shared__ int sh_c, sh_base;
    int b = blockIdx.x, t = threadIdx.x;
    int nbase = b * n_cur;
    int me = me_o[b];
    float bp0 = bp[0];
    // 0. stage graph data into smem (one node per thread; CSR copy vectorized)
    if (t < n_cur) {
        int g = nbase + t;
        rp[t] = rp_o[g];
        cn[t] = cnt_o[g];
        ds[t] = dis_o[g];
        sxw[t] = sxws_g[g];
    }
    {
        const uint4* src4 = (const uint4*)(csr_o + (size_t)b * EPG);
        uint4* dst4 = (uint4*)cs;
        int n8 = (me + 7) >> 3;               // u16 x8 per uint4
        for (int e = t; e < n8; e += 1024) dst4[e] = src4[e];
    }
    __syncthreads();
    // 1. scores (all smem)
    if (t < n_cur) {
        int st = rp[t], dc = cn[t];
        float acc = sxw[t];
        for (int q = 0; q < dc; q++) acc += sxw[cs[st + q]];
        float s = bp0 + ds[t] * acc;
        sc[t] = s;
        su[t] = encf(s);
    }
    __syncthreads();
    // 2. radix select ascending rank R = n_cur - k (the k-th largest key)
    int R = n_cur - k;
    unsigned prefix = 0, maskhi = 0;
#pragma unroll
    for (int pass = 3; pass >= 0; pass--) {
        int shift = pass * 8;
        if (t < 256) hist[t] = 0;
        __syncthreads();
        if (t < n_cur) {
            unsigned u = su[t];
            if ((u & maskhi) == prefix) atomicAdd(&hist[(u >> shift) & 255], 1);
        }
        __syncthreads();
        if (t < 32) {
            int loc[8];
            int s = 0;
#pragma unroll
            for (int j = 0; j < 8; j++) { loc[j] = hist[t * 8 + j]; s += loc[j]; }
            int v = s;
#pragma unroll
            for (int off = 1; off < 32; off <<= 1) {
                int u2 = __shfl_up_sync(0xffffffffu, v, off);
                if ((t & 31) >= off) v += u2;
            }
            int run = v - s;
#pragma unroll
            for (int j = 0; j < 8; j++) {
                if (R >= run && R < run + loc[j]) { sh_c = t * 8 + j; sh_base = run; }
                run += loc[j];
            }
        }
        __syncthreads();
        prefix |= ((unsigned)sh_c) << shift;
        maskhi |= 0xFFu << shift;
        R -= sh_base;
        __syncthreads();
    }
    unsigned thr = prefix;
    // 3. selection flags (gt<<16 | eq), stable compaction by index
    if (t < n_cur) {
        unsigned u = su[t];
        sflag[t] = (((u > thr) ? 1 : 0) << 16) | ((u == thr) ? 1 : 0);
    } else {
        sflag[t] = 0;
    }
    __syncthreads();
    block_exscan_1t(sflag, warpsums, t);
    int tot = warpsums[31];
    int quota = k - (tot >> 16);
    if (t < n_cur) {
        unsigned u = su[t];
        int ex = sflag[t];
        int gtex = ex >> 16, eqex = ex & 0xFFFF;
        int sel = -1;
        if (u > thr) sel = gtex + (eqex < quota ? eqex : quota);
        else if (u == thr && eqex < quota) sel = gtex + eqex;
        nidx[t] = sel;
        if (sel >= 0) oldof[sel] = t;
    } else {
        nidx[t] = -1;
    }
    __syncthreads();
    if (write_next) {
        // 4a. gates + perm for the next stage's gather-GEMM
        if (t < n_cur) {
            int sel = nidx[t];
            if (sel >= 0) {
                perm_g[b * k + sel] = nbase + t;
                gate_g[b * k + sel] = tanhf(sc[t]);
            }
        }
        __syncthreads();
        // 5. surviving-neighbor counts per new node (smem walk)
        if (t < k) {
            int ol = oldof[t];
            int st = rp[ol], dc = cn[ol];
            int c = 0;
            for (int q = 0; q < dc; q++)
                if (nidx[cs[st + q]] >= 0) c++;
            sflag[t] = c;
            cnt_n[b * k + t] = c;
            dis_n[b * k + t] = rsqrtf((float)c + 1.0f);
        } else {
            sflag[t] = 0;
        }
        __syncthreads();
        block_exscan_1t(sflag, warpsums, t);
        if (t == 0) me_n[b] = warpsums[31];
        // 6. write filtered + renamed CSR (u16 local)
        if (t < k) {
            int ex = sflag[t];
            rp_n[b * k + t] = ex;  // graph-local
            int ol = oldof[t];
            int st = rp[ol], dc = cn[ol];
            size_t p = (size_t)b * EPG + ex;
            for (int q = 0; q < dc; q++) {
                int nl = nidx[cs[st + q]];
                if (nl >= 0) csr_n[p++] = (u16)nl;
            }
        }
    } else {
        // 4b. final stage: gates by NEW id (su reused), then fused readout
        if (t < n_cur) {
            int sel = nidx[t];
            if (sel >= 0) su[sel] = __float_as_uint(tanhf(sc[t]));
        }
        __syncthreads();
        int rg = t >> 6, f = t & 63;       // 16 row groups x 64 features
        float mx = -3.402823466e+38f, sm = 0.f;
        for (int j = rg; j < k; j += 16) {
            int ol = oldof[j];
            float v = A[(size_t)(nbase + ol) * 64 + f] * __uint_as_float(su[j]);
            mx = fmaxf(mx, v);
            sm += v;
        }
        float* rred = (float*)sflag;       // reuse scan buffer
        rred[t] = mx;
        __syncthreads();
        if (t < 64) {
            float m = rred[t];
#pragma unroll
            for (int r = 1; r < 16; r++) m = fmaxf(m, rred[t + 64 * r]);
            ((unsigned*)rbuf)[b * 128 + f] = encf(m);
        }
        __syncthreads();
        rred[t] = sm;
        __syncthreads();
        if (t < 64) {
            float s = rred[t];
#pragma unroll
            for (int r = 1; r < 16; r++) s += rred[t + 64 * r];
            rbuf[b * 128 + 64 + f] = s;    // raw sum; mlp divides by K3
        }
    }
}

// ---------------- final MLP (decodes encoded rbufs) ----------------
__global__ void k_mlp(const float* __restrict__ r1, const float* __restrict__ r2,
                      const float* __restrict__ r3,
                      const float* __restrict__ L1w, const float* __restrict__ L1b,
                      const float* __restrict__ L2w, const float* __restrict__ L2b,
                      const float* __restrict__ L3w, const float* __restrict__ L3b,
                      float* __restrict__ out) {
    __shared__ float zs[128], h1[64], h2[32], os[10];
    __shared__ float lse;
    int b = blockIdx.x, t = threadIdx.x;
    const unsigned* r1u = (const unsigned*)r1;
    const unsigned* r2u = (const unsigned*)r2;
    const unsigned* r3u = (const unsigned*)r3;
    zs[t] = decf(r1u[b * 128 + t]) + decf(r2u[b * 128 + t]) + decf(r3u[b * 128 + t]);
    zs[t + 64] = r1[b * 128 + 64 + t] / (float)K1 +
                 r2[b * 128 + 64 + t] / (float)K2 +
                 r3[b * 128 + 64 + t] / (float)K3;
    __syncthreads();
    {
        float acc = L1b[t];
        for (int j = 0; j < 128; j++) acc += zs[j] * L1w[j * 64 + t];
        h1[t] = fmaxf(acc, 0.f);
    }
    __syncthreads();
    if (t < 32) {
        float a = L2b[t];
        for (int j = 0; j < 64; j++) a += h1[j] * L2w[j * 32 + t];
        h2[t] = fmaxf(a, 0.f);
    }
    __syncthreads();
    if (t < 10) {
        float a = L3b[t];
        for (int j = 0; j < 32; j++) a += h2[j] * L3w[j * 10 + t];
        os[t] = a;
    }
    __syncthreads();
    if (t == 0) {
        float mx = os[0];
        for (int j = 1; j < 10; j++) mx = fmaxf(mx, os[j]);
        float s = 0.f;
        for (int j = 0; j < 10; j++) s += expf(os[j] - mx);
        lse = mx + logf(s);
    }
    __syncthreads();
    if (t < 10) out[b * 10 + t] = os[t] - lse;
}

// ---------------- host orchestration ----------------
extern "C" void kernel_launch(void* const* d_in, const int* in_sizes, int n_in,
                              void* d_out, int out_size) {
    const float* x   = (const float*)d_in[0];
    const int* esrc  = (const int*)d_in[1];
    const int* edst  = (const int*)d_in[2];
    const float* W1  = (const float*)d_in[3];
    const float* b1  = (const float*)d_in[4];
    const float* Wp1 = (const float*)d_in[5];
    const float* bp1 = (const float*)d_in[6];
    const float* W2  = (const float*)d_in[7];
    const float* b2  = (const float*)d_in[8];
    const float* Wp2 = (const float*)d_in[9];
    const float* bp2 = (const float*)d_in[10];
    const float* W3  = (const float*)d_in[11];
    const float* b3  = (const float*)d_in[12];
    const float* Wp3 = (const float*)d_in[13];
    const float* bp3 = (const float*)d_in[14];
    const float* L1w = (const float*)d_in[15];
    const float* L1b = (const float*)d_in[16];
    const float* L2w = (const float*)d_in[17];
    const float* L2b = (const float*)d_in[18];
    const float* L3w = (const float*)d_in[19];
    const float* L3b = (const float*)d_in[20];
    float* out = (float*)d_out;

    cudaFuncSetAttribute(k_pool, cudaFuncAttributeMaxDynamicSharedMemorySize,
                         POOL_SMEM);

    float *pA, *pxw, *pdisA, *pdisB, *psxws, *pgate, *pr1, *pr2, *pr3;
    int *prpA, *prpB, *pcntA, *pcntB, *pmeA, *pmeB, *pperm;
    u16 *pcsrA, *pcsrB;
    cudaGetSymbolAddress((void**)&pA, g_A);
    cudaGetSymbolAddress((void**)&pxw, g_xw);
    cudaGetSymbolAddress((void**)&pdisA, g_disA);
    cudaGetSymbolAddress((void**)&pdisB, g_disB);
    cudaGetSymbolAddress((void**)&psxws, g_sxws);
    cudaGetSymbolAddress((void**)&pgate, g_gate);
    cudaGetSymbolAddress((void**)&pperm, g_perm);
    cudaGetSymbolAddress((void**)&prpA, g_rpA);
    cudaGetSymbolAddress((void**)&prpB, g_rpB);
    cudaGetSymbolAddress((void**)&pcntA, g_cntA);
    cudaGetSymbolAddress((void**)&pcntB, g_cntB);
    cudaGetSymbolAddress((void**)&pcsrA, g_csrA);
    cudaGetSymbolAddress((void**)&pcsrB, g_csrB);
    cudaGetSymbolAddress((void**)&pmeA, g_meA);
    cudaGetSymbolAddress((void**)&pmeB, g_meB);
    cudaGetSymbolAddress((void**)&pr1, g_r1);
    cudaGetSymbolAddress((void**)&pr2, g_r2);
    cudaGetSymbolAddress((void**)&pr3, g_r3);

    // CSR build + readout-accumulator zeroing (no separate memsets)
    k_csr0<<<BGRAPHS, 1024>>>(esrc, edst, prpA, pcntA, pdisA, pcsrA, pmeA,
                              pr1, pr2, pr3);

    // ---- stage 1 ----
    k_gemm64g<false><<<NT1 / 64, 256>>>(x, W1, pdisA, nullptr, nullptr, pxw,
                                        nullptr, 0);
    k_agg<<<NT1 / 8, 256>>>((const float2*)pxw, prpA, pcntA, pdisA, pcsrA,
                            b1, Wp1, (float2*)pA, psxws, NT1, N0);
    k_pool<<<BGRAPHS, 1024, POOL_SMEM>>>(pA, psxws, pdisA, prpA, pcntA, pcsrA,
                                         pmeA, bp1, N0, K1, 1, pperm, pgate,
                                         nullptr, prpB, pcntB, pdisB, pcsrB, pmeB);

    // ---- stage 2 (gemm computes r1 from its gathered+gated As tiles) ----
    k_gemm64g<true><<<NT2 / 64, 256>>>(pA, W2, pdisB, pperm, pgate, pxw, pr1, K1);
    k_agg<<<NT2 / 8, 256>>>((const float2*)pxw, prpB, pcntB, pdisB, pcsrB,
                            b2, Wp2, (float2*)pA, psxws, NT2, K1);
    k_pool<<<BGRAPHS, 1024, POOL_SMEM>>>(pA, psxws, pdisB, prpB, pcntB, pcsrB,
                                         pmeB, bp2, K1, K2, 1, pperm, pgate,
                                         nullptr, prpA, pcntA, pdisA, pcsrA, pmeA);

    // ---- stage 3 (gemm computes r2; pool computes r3 via fused readout) ----
    k_gemm64g<true><<<NT3 / 64, 256>>>(pA, W3, pdisA, pperm, pgate, pxw, pr2, K2);
    k_agg<<<NT3 / 8, 256>>>((const float2*)pxw, prpA, pcntA, pdisA, pcsrA,
                            b3, Wp3, (float2*)pA, psxws, NT3, K2);
    k_pool<<<BGRAPHS, 1024, POOL_SMEM>>>(pA, psxws, pdisA, prpA, pcntA, pcsrA,
                                         pmeA, bp3, K2, K3, 0, pperm, pgate,
                                         pr3, prpB, pcntB, pdisB, pcsrB, pmeB);

    k_mlp<<<BGRAPHS, 64>>>(pr1, pr2, pr3, L1w, L1b, L2w, L2b, L3w, L3b, out);
}